// round 2
// baseline (speedup 1.0000x reference)
#include <cuda_runtime.h>

#define N_DIM 8192
#define ROW4 (N_DIM / 4)          // 2048 float4 per row
#define TOTAL4 (N_DIM * ROW4)     // 16,777,216 float4 elements
#define GRID 4096
#define TPB 256

// Per-block partial sums (allocation-free __device__ scratch; written every
// launch before being read, so no init needed).
__device__ float g_partAbs[GRID];
__device__ float g_partCW[GRID];
__device__ float g_partW[GRID];
// Ticket counter: starts 0 (static init), reset to 0 by the last block each
// launch -> deterministic across graph replays.
__device__ unsigned g_ticket = 0;

__global__ __launch_bounds__(TPB) void parietal_fused_kernel(
    const float*  __restrict__ a,       // [N_DIM] neural activities
    const float4* __restrict__ W4,      // [N*N/4] connection matrix
    const float4* __restrict__ Cin4,    // [N*N/4] correlation matrix (in)
    float4*       __restrict__ Cout4,   // [N*N/4] C (out)
    const float*  __restrict__ coh_in,  // [1] coherence_strength
    const float*  __restrict__ integ_in,// [1] integration_measure
    float*        __restrict__ out_tail)// d_out + N*N (3 floats)
{
    const float decay = 0.9f;
    const float one_minus = 0.1f;

    float sAbs = 0.0f, sCW = 0.0f, sW = 0.0f;

    const int stride = GRID * TPB;
    for (int idx4 = blockIdx.x * TPB + threadIdx.x; idx4 < TOTAL4; idx4 += stride) {
        const int i  = idx4 >> 11;      // row (ROW4 = 2048 = 1<<11)
        const int j4 = idx4 & 2047;     // float4-column

        const float4 c = Cin4[idx4];
        const float4 w = W4[idx4];
        const float  ai = __ldg(&a[i]);
        const float4 aj = reinterpret_cast<const float4*>(a)[j4];

        // diagonal element falls in this float4 iff i/4 == j4; lane = i&3
        const int diagLane = ((i >> 2) == j4) ? (i & 3) : -1;

        float o0 = (diagLane == 0) ? c.x : fmaf(one_minus * ai, aj.x, decay * c.x);
        float o1 = (diagLane == 1) ? c.y : fmaf(one_minus * ai, aj.y, decay * c.y);
        float o2 = (diagLane == 2) ? c.z : fmaf(one_minus * ai, aj.z, decay * c.z);
        float o3 = (diagLane == 3) ? c.w : fmaf(one_minus * ai, aj.w, decay * c.w);

        const float a0 = fabsf(o0), a1 = fabsf(o1), a2 = fabsf(o2), a3 = fabsf(o3);

        sAbs += (a0 + a1) + (a2 + a3);
        sW   += (w.x + w.y) + (w.z + w.w);
        sCW  += (a0 * w.x + a1 * w.y) + (a2 * w.z + a3 * w.w);

        Cout4[idx4] = make_float4(o0, o1, o2, o3);
    }

    // ---- block reduction (warp shuffle + smem) ----
    #pragma unroll
    for (int off = 16; off > 0; off >>= 1) {
        sAbs += __shfl_down_sync(0xFFFFFFFFu, sAbs, off);
        sCW  += __shfl_down_sync(0xFFFFFFFFu, sCW,  off);
        sW   += __shfl_down_sync(0xFFFFFFFFu, sW,   off);
    }

    __shared__ float redAbs[8], redCW[8], redW[8];
    __shared__ bool  sh_isLast;
    const int lane = threadIdx.x & 31;
    const int wid  = threadIdx.x >> 5;
    if (lane == 0) { redAbs[wid] = sAbs; redCW[wid] = sCW; redW[wid] = sW; }
    __syncthreads();

    if (threadIdx.x == 0) {
        float bAbs = 0.0f, bCW = 0.0f, bW = 0.0f;
        #pragma unroll
        for (int k = 0; k < TPB / 32; k++) {
            bAbs += redAbs[k]; bCW += redCW[k]; bW += redW[k];
        }
        g_partAbs[blockIdx.x] = bAbs;
        g_partCW[blockIdx.x]  = bCW;
        g_partW[blockIdx.x]   = bW;
        __threadfence();
        unsigned t = atomicAdd(&g_ticket, 1u);
        sh_isLast = (t == GRID - 1);
    }
    __syncthreads();

    // ---- last block: final reduction + scalar epilogue ----
    if (sh_isLast) {
        float fAbs = 0.0f, fCW = 0.0f, fW = 0.0f;
        for (int k = threadIdx.x; k < GRID; k += TPB) {
            fAbs += g_partAbs[k];
            fCW  += g_partCW[k];
            fW   += g_partW[k];
        }
        #pragma unroll
        for (int off = 16; off > 0; off >>= 1) {
            fAbs += __shfl_down_sync(0xFFFFFFFFu, fAbs, off);
            fCW  += __shfl_down_sync(0xFFFFFFFFu, fCW,  off);
            fW   += __shfl_down_sync(0xFFFFFFFFu, fW,   off);
        }
        if (lane == 0) { redAbs[wid] = fAbs; redCW[wid] = fCW; redW[wid] = fW; }
        __syncthreads();

        if (threadIdx.x == 0) {
            double corr_sum = 0.0, cw_sum = 0.0, w_sum = 0.0;
            #pragma unroll
            for (int k = 0; k < TPB / 32; k++) {
                corr_sum += (double)redAbs[k];
                cw_sum   += (double)redCW[k];
                w_sum    += (double)redW[k];
            }

            const double n_conn = (double)N_DIM * (double)(N_DIM - 1);
            float coherence = 0.9f * coh_in[0] + 0.1f * (float)(corr_sum / n_conn);

            float integration;
            if (w_sum > 0.0) {
                integration = 0.9f * integ_in[0] + 0.1f * (float)(cw_sum / w_sum);
            } else {
                integration = integ_in[0];
            }

            const double n_total = (double)N_DIM * (double)N_DIM;
            float synchrony = (float)(corr_sum / n_total);

            out_tail[0] = coherence;
            out_tail[1] = integration;
            out_tail[2] = synchrony;

            g_ticket = 0;   // reset for next (deterministic) launch/replay
        }
    }
}

extern "C" void kernel_launch(void* const* d_in, const int* in_sizes, int n_in,
                              void* d_out, int out_size) {
    const float* a     = (const float*)d_in[0];   // neural_activities [8192]
    const float* W     = (const float*)d_in[1];   // connection_matrix [8192*8192]
    const float* Cin   = (const float*)d_in[2];   // correlation_matrix [8192*8192]
    const float* coh   = (const float*)d_in[3];   // coherence_strength [1]
    const float* integ = (const float*)d_in[4];   // integration_measure [1]

    float* out = (float*)d_out;   // [N*N] C, then coherence, integration, synchrony

    parietal_fused_kernel<<<GRID, TPB>>>(
        a,
        (const float4*)W,
        (const float4*)Cin,
        (float4*)out,
        coh, integ,
        out + (size_t)N_DIM * N_DIM);
}